// round 11
// baseline (speedup 1.0000x reference)
#include <cuda_runtime.h>
#include <cuda_fp16.h>
#include <math.h>
#include <stdint.h>

#define F 128
#define MAXN 50000
#define MAXEGO 1250000
#define MAXE 700000
#define SCAN_TILE 1024
#define MAX_TILES 64

// fp16 activation buffers
__device__ __half g_xb[MAXN * F];
__device__ __half g_yb0[MAXN * F];
__device__ __half g_yb1[MAXN * F];
__device__ __half g_ah[MAXN * F];
// CSR scratch (list 0 = ego, list 1 = gin edges)
__device__ int g_deg[2 * MAXN];
__device__ int g_off[2 * (MAXN + 1)];
__device__ int g_cur[2 * MAXN];
__device__ int g_adjEgo[MAXEGO];
__device__ int g_adjE[MAXE];
__device__ int g_part[2 * MAX_TILES];

// ---------------------------------------------------------------------------
// fused: histogram both edge lists (4 edges/thread, MLP) + fp32->fp16 convert.
__global__ void build_front_kernel(const int* __restrict__ w0, int n0,
                                   const int* __restrict__ w1, int n1,
                                   int* __restrict__ deg0, int* __restrict__ deg1,
                                   const float* __restrict__ x, __half* __restrict__ y,
                                   int n4) {
    int tid = blockIdx.x * blockDim.x + threadIdx.x;
    int t4 = tid * 4;
    if (t4 + 3 < n0) {
        int4 w = __ldg((const int4*)(w0 + t4));
        atomicAdd(&deg0[w.x], 1); atomicAdd(&deg0[w.y], 1);
        atomicAdd(&deg0[w.z], 1); atomicAdd(&deg0[w.w], 1);
    } else {
#pragma unroll
        for (int j = 0; j < 4; j++)
            if (t4 + j < n0) atomicAdd(&deg0[__ldg(w0 + t4 + j)], 1);
    }
    if (t4 + 3 < n1) {
        int4 w = __ldg((const int4*)(w1 + t4));
        atomicAdd(&deg1[w.x], 1); atomicAdd(&deg1[w.y], 1);
        atomicAdd(&deg1[w.z], 1); atomicAdd(&deg1[w.w], 1);
    } else {
#pragma unroll
        for (int j = 0; j < 4; j++)
            if (t4 + j < n1) atomicAdd(&deg1[__ldg(w1 + t4 + j)], 1);
    }
    for (int j = tid; j < n4; j += gridDim.x * blockDim.x) {
        float4 v = ((const float4*)x)[j];
        __half2 h0 = __floats2half2_rn(v.x, v.y);
        __half2 h1 = __floats2half2_rn(v.z, v.w);
        uint2 u;
        u.x = *(uint32_t*)&h0; u.y = *(uint32_t*)&h1;
        ((uint2*)y)[j] = u;
    }
}

// ---------------------------------------------------------------------------
// 2-phase exclusive scan, two lists via blockIdx.y.
__global__ void scan_p1_kernel(const int* __restrict__ deg, int n,
                               int* __restrict__ part, int ntiles) {
    __shared__ int ws[8];
    const int* d = deg + blockIdx.y * n;
    int* p = part + blockIdx.y * ntiles;
    int b = blockIdx.x, t = threadIdx.x;
    int base = b * SCAN_TILE + t * 4;
    int s = 0;
#pragma unroll
    for (int j = 0; j < 4; j++) {
        int i = base + j;
        if (i < n) s += __ldg(d + i);
    }
    int lane = t & 31, wid = t >> 5;
#pragma unroll
    for (int o = 16; o; o >>= 1) s += __shfl_down_sync(0xffffffffu, s, o);
    if (lane == 0) ws[wid] = s;
    __syncthreads();
    if (t < 8) {
        int v = ws[t];
#pragma unroll
        for (int o = 4; o; o >>= 1) v += __shfl_down_sync(0xffu, v, o);
        if (t == 0) p[b] = v;
    }
}

// p3 with in-block scan of partials. nb = #tiles (<=64).
__global__ void scan_p3_kernel(const int* __restrict__ deg, int n,
                               const int* __restrict__ part,
                               int* __restrict__ off, int* __restrict__ cur,
                               int ntiles, int nb) {
    __shared__ int ws[8];
    __shared__ int wtot[2];
    __shared__ int psc[MAX_TILES + 1];
    const int list = blockIdx.y;
    const int* d = deg + list * n;
    int* of = off + list * (n + 1);
    int* cu = cur + list * n;
    int b = blockIdx.x, t = threadIdx.x;

    int px = 0;
    if (t < 64) {
        int pv = (t < nb) ? __ldg(part + list * ntiles + t) : 0;
        int lane = t & 31, w = t >> 5;
        px = pv;
#pragma unroll
        for (int o = 1; o < 32; o <<= 1) {
            int u = __shfl_up_sync(0xffffffffu, px, o);
            if (lane >= o) px += u;
        }
        if (lane == 31) wtot[w] = px;
    }
    __syncthreads();
    if (t < 64) {
        int incl = px + ((t >> 5) ? wtot[0] : 0);
        psc[t + 1] = incl;
        if (t == 0) psc[0] = 0;
    }
    __syncthreads();
    if (b == 0 && t == 0) of[n] = psc[nb];
    const int tilebase = psc[b];

    int base = b * SCAN_TILE + t * 4;
    int v[4];
    int s = 0;
#pragma unroll
    for (int j = 0; j < 4; j++) {
        int i = base + j;
        v[j] = (i < n) ? __ldg(d + i) : 0;
        s += v[j];
    }
    int lane = t & 31, wid = t >> 5;
    int x = s;
#pragma unroll
    for (int o = 1; o < 32; o <<= 1) {
        int u = __shfl_up_sync(0xffffffffu, x, o);
        if (lane >= o) x += u;
    }
    if (lane == 31) ws[wid] = x;
    __syncthreads();
    if (wid == 0) {
        int w = (lane < 8) ? ws[lane] : 0;
#pragma unroll
        for (int o = 1; o < 8; o <<= 1) {
            int u = __shfl_up_sync(0xffffffffu, w, o);
            if (lane >= o) w += u;
        }
        if (lane < 8) ws[lane] = w;
    }
    __syncthreads();
    int run = tilebase + (x - s) + (wid ? ws[wid - 1] : 0);
#pragma unroll
    for (int j = 0; j < 4; j++) {
        int i = base + j;
        if (i < n) { of[i] = run; cu[i] = run; }
        run += v[j];
    }
}

// fill with 4 edges/thread: int4 index loads, 4 independent atomic chains.
__global__ void fill2_kernel(const int* __restrict__ w0, const int* __restrict__ r0, int n0,
                             const int* __restrict__ w1, const int* __restrict__ r1, int n1,
                             int* __restrict__ cur0, int* __restrict__ cur1,
                             int* __restrict__ adj0, int* __restrict__ adj1) {
    int t4 = (blockIdx.x * blockDim.x + threadIdx.x) * 4;
    if (t4 + 3 < n0) {
        int4 w = __ldg((const int4*)(w0 + t4));
        int4 r = __ldg((const int4*)(r0 + t4));
        int p0 = atomicAdd(&cur0[w.x], 1);
        int p1 = atomicAdd(&cur0[w.y], 1);
        int p2 = atomicAdd(&cur0[w.z], 1);
        int p3 = atomicAdd(&cur0[w.w], 1);
        adj0[p0] = r.x; adj0[p1] = r.y; adj0[p2] = r.z; adj0[p3] = r.w;
    } else {
#pragma unroll
        for (int j = 0; j < 4; j++) {
            int i = t4 + j;
            if (i < n0) {
                int pos = atomicAdd(&cur0[__ldg(w0 + i)], 1);
                adj0[pos] = __ldg(r0 + i);
            }
        }
    }
    if (t4 + 3 < n1) {
        int4 w = __ldg((const int4*)(w1 + t4));
        int4 r = __ldg((const int4*)(r1 + t4));
        int p0 = atomicAdd(&cur1[w.x], 1);
        int p1 = atomicAdd(&cur1[w.y], 1);
        int p2 = atomicAdd(&cur1[w.z], 1);
        int p3 = atomicAdd(&cur1[w.w], 1);
        adj1[p0] = r.x; adj1[p1] = r.y; adj1[p2] = r.z; adj1[p3] = r.w;
    } else {
#pragma unroll
        for (int j = 0; j < 4; j++) {
            int i = t4 + j;
            if (i < n1) {
                int pos = atomicAdd(&cur1[__ldg(w1 + i)], 1);
                adj1[pos] = __ldg(r1 + i);
            }
        }
    }
}

// ---------------------------------------------------------------------------
__device__ __forceinline__ void addh2(float2& a, uint32_t h) {
    float2 f = __half22float2(*(__half2*)&h);
    a.x += f.x; a.y += f.y;
}

// segsum over CSR, fp16 rows (uint2/lane) -> fp16 out. fp32 accumulate.
template <bool SELF>
__global__ void segsum128h_kernel(const __half* __restrict__ x,
                                  const int* __restrict__ off,
                                  const int* __restrict__ adj,
                                  __half* __restrict__ out, int n, float scale) {
    int gw = (blockIdx.x * blockDim.x + threadIdx.x) >> 5;
    int lane = threadIdx.x & 31;
    if (gw >= n) return;
    int s = __ldg(off + gw), e = __ldg(off + gw + 1);
    float2 acc0 = make_float2(0.f, 0.f), acc1 = make_float2(0.f, 0.f);
    if (SELF) {
        uint2 sv = __ldg((const uint2*)(x + (size_t)gw * 128) + lane);
        addh2(acc0, sv.x); addh2(acc1, sv.y);
    }
    for (int j = s; j < e; ) {
        int cnt = min(32, e - j);
        int my = (lane < cnt) ? __ldg(adj + j + lane) : 0;
        int k = 0;
        for (; k + 4 <= cnt; k += 4) {
            int r0 = __shfl_sync(0xffffffffu, my, k);
            int r1 = __shfl_sync(0xffffffffu, my, k + 1);
            int r2 = __shfl_sync(0xffffffffu, my, k + 2);
            int r3 = __shfl_sync(0xffffffffu, my, k + 3);
            uint2 u0 = __ldg((const uint2*)(x + (size_t)r0 * 128) + lane);
            uint2 u1 = __ldg((const uint2*)(x + (size_t)r1 * 128) + lane);
            uint2 u2 = __ldg((const uint2*)(x + (size_t)r2 * 128) + lane);
            uint2 u3 = __ldg((const uint2*)(x + (size_t)r3 * 128) + lane);
            addh2(acc0, u0.x); addh2(acc1, u0.y);
            addh2(acc0, u1.x); addh2(acc1, u1.y);
            addh2(acc0, u2.x); addh2(acc1, u2.y);
            addh2(acc0, u3.x); addh2(acc1, u3.y);
        }
        for (; k < cnt; k++) {
            int r0 = __shfl_sync(0xffffffffu, my, k);
            uint2 u0 = __ldg((const uint2*)(x + (size_t)r0 * 128) + lane);
            addh2(acc0, u0.x); addh2(acc1, u0.y);
        }
        j += cnt;
    }
    __half2 h0 = __floats2half2_rn(acc0.x * scale, acc0.y * scale);
    __half2 h1 = __floats2half2_rn(acc1.x * scale, acc1.y * scale);
    uint2 o;
    o.x = *(uint32_t*)&h0; o.y = *(uint32_t*)&h1;
    *(uint2*)(out + (size_t)gw * 128 + lane * 4) = o;
}

// ---------------------------------------------------------------------------
__device__ __forceinline__ void mma_f16(float& c0, float& c1, float& c2, float& c3,
                                        uint32_t a0, uint32_t a1, uint32_t a2, uint32_t a3,
                                        uint32_t b0, uint32_t b1) {
    asm volatile(
        "mma.sync.aligned.m16n8k16.row.col.f32.f16.f16.f32 "
        "{%0,%1,%2,%3}, {%4,%5,%6,%7}, {%8,%9}, {%0,%1,%2,%3};"
        : "+f"(c0), "+f"(c1), "+f"(c2), "+f"(c3)
        : "r"(a0), "r"(a1), "r"(a2), "r"(a3), "r"(b0), "r"(b1));
}

// fp16 GEMM: C = relu(Ah @ W + b), 64x64 tile per CTA, grid.y = col tile of 64.
__global__ void __launch_bounds__(256, 4)
gemm_h_kernel(const __half* __restrict__ Ah,
              const float* __restrict__ W, const float* __restrict__ bias,
              __half* __restrict__ Ch, int M) {
    constexpr int PWH = 136;
    constexpr int PAH = 136;
    __shared__ __half Wt[64 * PWH];
    __shared__ __half As[64 * PAH];
    __shared__ float bs[64];

    const int tid  = threadIdx.x;
    const int lane = tid & 31;
    const int warp = tid >> 5;
    const int cb   = blockIdx.y * 64;
    const int base = blockIdx.x * 64;

    {
        int tn = tid & 63;
        int gc = cb + tn;
        for (int kb = (tid >> 6) * 8; kb < 128; kb += 32) {
            __half tmp[8];
#pragma unroll
            for (int j = 0; j < 8; j++)
                tmp[j] = __float2half_rn(__ldg(W + (size_t)(kb + j) * 128 + gc));
            *(uint4*)(Wt + tn * PWH + kb) = *(uint4*)tmp;
        }
    }
    if (tid < 64) bs[tid] = __ldg(bias + cb + tid);

#pragma unroll
    for (int u = tid; u < 64 * 16; u += 256) {
        int rr = u >> 4, c8 = u & 15;
        int row = base + rr;
        uint4 hv = make_uint4(0u, 0u, 0u, 0u);
        if (row < M) hv = __ldg((const uint4*)(Ah + (size_t)row * 128) + c8);
        *(uint4*)(As + rr * PAH + c8 * 8) = hv;
    }
    __syncthreads();

    const int wr = warp >> 1, wc = warp & 1;
    const int g = lane >> 2, t = lane & 3;
    float acc[4][4];
#pragma unroll
    for (int nt = 0; nt < 4; nt++)
#pragma unroll
        for (int j = 0; j < 4; j++) acc[nt][j] = 0.f;

    const int r0 = wr * 16 + g;
    const __half* arow0 = As + r0 * PAH;
    const __half* arow1 = As + (r0 + 8) * PAH;
#pragma unroll
    for (int ks = 0; ks < 8; ks++) {
        const int k0 = ks * 16;
        uint32_t a0 = *(const uint32_t*)(arow0 + k0 + 2 * t);
        uint32_t a1 = *(const uint32_t*)(arow1 + k0 + 2 * t);
        uint32_t a2 = *(const uint32_t*)(arow0 + k0 + 2 * t + 8);
        uint32_t a3 = *(const uint32_t*)(arow1 + k0 + 2 * t + 8);
#pragma unroll
        for (int nt = 0; nt < 4; nt++) {
            int n = wc * 32 + nt * 8 + g;
            uint32_t b0 = *(const uint32_t*)(Wt + n * PWH + k0 + 2 * t);
            uint32_t b1 = *(const uint32_t*)(Wt + n * PWH + k0 + 2 * t + 8);
            mma_f16(acc[nt][0], acc[nt][1], acc[nt][2], acc[nt][3],
                    a0, a1, a2, a3, b0, b1);
        }
    }

    int gr0 = base + wr * 16 + g;
    int gr1 = gr0 + 8;
#pragma unroll
    for (int nt = 0; nt < 4; nt++) {
        int col = wc * 32 + nt * 8 + t * 2;
        float bx = bs[col], by = bs[col + 1];
        __half2 h0 = __floats2half2_rn(fmaxf(acc[nt][0] + bx, 0.f), fmaxf(acc[nt][1] + by, 0.f));
        __half2 h1 = __floats2half2_rn(fmaxf(acc[nt][2] + bx, 0.f), fmaxf(acc[nt][3] + by, 0.f));
        int gcol = cb + col;
        if (gr0 < M) *(__half2*)(Ch + (size_t)gr0 * 128 + gcol) = h0;
        if (gr1 < M) *(__half2*)(Ch + (size_t)gr1 * 128 + gcol) = h1;
    }
}

// final GEMM + bias + log_softmax fused: out = log_softmax(Ah @ W + b) (47 cols).
__global__ void __launch_bounds__(256, 4)
gemm47_lsm_kernel(const __half* __restrict__ Ah, const float* __restrict__ W,
                  const float* __restrict__ bias,
                  float* __restrict__ outp, int M, int nca) {
    constexpr int PWH = 136;
    constexpr int PAH = 136;
    constexpr int LP = 65;
    __shared__ __half Wt[64 * PWH];   // reused as logits after MMA
    __shared__ __half As[64 * PAH];
    __shared__ float bs[64];

    const int tid  = threadIdx.x;
    const int lane = tid & 31;
    const int warp = tid >> 5;
    const int base = blockIdx.x * 64;

    {
        int tn = tid & 63;
        for (int kb = (tid >> 6) * 8; kb < 128; kb += 32) {
            __half tmp[8];
#pragma unroll
            for (int j = 0; j < 8; j++) {
                float w = (tn < nca) ? __ldg(W + (size_t)(kb + j) * nca + tn) : 0.f;
                tmp[j] = __float2half_rn(w);
            }
            *(uint4*)(Wt + tn * PWH + kb) = *(uint4*)tmp;
        }
    }
    if (tid < 64) bs[tid] = (tid < nca) ? __ldg(bias + tid) : 0.f;
#pragma unroll
    for (int u = tid; u < 64 * 16; u += 256) {
        int rr = u >> 4, c8 = u & 15;
        int row = base + rr;
        uint4 hv = make_uint4(0u, 0u, 0u, 0u);
        if (row < M) hv = __ldg((const uint4*)(Ah + (size_t)row * 128) + c8);
        *(uint4*)(As + rr * PAH + c8 * 8) = hv;
    }
    __syncthreads();

    const int wr = warp >> 1, wc = warp & 1;
    const int g = lane >> 2, t = lane & 3;
    float acc[4][4];
#pragma unroll
    for (int nt = 0; nt < 4; nt++)
#pragma unroll
        for (int j = 0; j < 4; j++) acc[nt][j] = 0.f;

    const int r0 = wr * 16 + g;
    const __half* arow0 = As + r0 * PAH;
    const __half* arow1 = As + (r0 + 8) * PAH;
#pragma unroll
    for (int ks = 0; ks < 8; ks++) {
        const int k0 = ks * 16;
        uint32_t a0 = *(const uint32_t*)(arow0 + k0 + 2 * t);
        uint32_t a1 = *(const uint32_t*)(arow1 + k0 + 2 * t);
        uint32_t a2 = *(const uint32_t*)(arow0 + k0 + 2 * t + 8);
        uint32_t a3 = *(const uint32_t*)(arow1 + k0 + 2 * t + 8);
#pragma unroll
        for (int nt = 0; nt < 4; nt++) {
            int n = wc * 32 + nt * 8 + g;
            uint32_t b0 = *(const uint32_t*)(Wt + n * PWH + k0 + 2 * t);
            uint32_t b1 = *(const uint32_t*)(Wt + n * PWH + k0 + 2 * t + 8);
            mma_f16(acc[nt][0], acc[nt][1], acc[nt][2], acc[nt][3],
                    a0, a1, a2, a3, b0, b1);
        }
    }
    __syncthreads();  // all Wt reads done; reuse as logits

    float* lg = (float*)Wt;  // [64][LP]
#pragma unroll
    for (int nt = 0; nt < 4; nt++) {
        int col = wc * 32 + nt * 8 + t * 2;
        float bx = bs[col], by = bs[col + 1];
        int lr0 = wr * 16 + g, lr1 = lr0 + 8;
        lg[lr0 * LP + col]     = acc[nt][0] + bx;
        lg[lr0 * LP + col + 1] = acc[nt][1] + by;
        lg[lr1 * LP + col]     = acc[nt][2] + bx;
        lg[lr1 * LP + col + 1] = acc[nt][3] + by;
    }
    __syncthreads();

    for (int r = warp; r < 64; r += 8) {
        int row = base + r;
        if (row >= M) continue;
        int c2 = lane + 32;
        float v1 = (lane < nca) ? lg[r * LP + lane] : -INFINITY;
        float v2 = (c2 < nca)   ? lg[r * LP + c2]   : -INFINITY;
        float mx = fmaxf(v1, v2);
#pragma unroll
        for (int o = 16; o; o >>= 1) mx = fmaxf(mx, __shfl_xor_sync(0xffffffffu, mx, o));
        float s = ((lane < nca) ? expf(v1 - mx) : 0.f) + ((c2 < nca) ? expf(v2 - mx) : 0.f);
#pragma unroll
        for (int o = 16; o; o >>= 1) s += __shfl_xor_sync(0xffffffffu, s, o);
        float lgn = logf(s) + mx;
        float* orow = outp + (size_t)row * nca;
        if (lane < nca) orow[lane] = v1 - lgn;
        if (c2 < nca)   orow[c2]   = v2 - lgn;
    }
}

// ---------------------------------------------------------------------------
extern "C" void kernel_launch(void* const* d_in, const int* in_sizes, int n_in,
                              void* d_out, int out_size) {
    const float* x_in   = (const float*)d_in[0];
    const int*   ei     = (const int*)d_in[1];
    const int*   ego    = (const int*)d_in[2];
    const float* W_ego0 = (const float*)d_in[3];
    const float* b_ego0 = (const float*)d_in[4];
    const float* W_gin0 = (const float*)d_in[5];
    const float* b_gin0 = (const float*)d_in[6];
    const float* W_ego1 = (const float*)d_in[7];
    const float* b_ego1 = (const float*)d_in[8];
    const float* W_gin1 = (const float*)d_in[9];
    const float* b_gin1 = (const float*)d_in[10];

    int N    = in_sizes[0] / F;
    int E    = in_sizes[1] / 2;
    int EGO  = in_sizes[2] / 2;
    int OUTC = in_sizes[10];
    float invN = 1.0f / (float)N;

    __half *xb, *yb0, *yb1, *ah;
    int *deg, *off, *cur, *adjEgo, *adjE, *part;
    cudaGetSymbolAddress((void**)&xb, g_xb);
    cudaGetSymbolAddress((void**)&yb0, g_yb0);
    cudaGetSymbolAddress((void**)&yb1, g_yb1);
    cudaGetSymbolAddress((void**)&ah, g_ah);
    cudaGetSymbolAddress((void**)&deg, g_deg);
    cudaGetSymbolAddress((void**)&off, g_off);
    cudaGetSymbolAddress((void**)&cur, g_cur);
    cudaGetSymbolAddress((void**)&adjEgo, g_adjEgo);
    cudaGetSymbolAddress((void**)&adjE, g_adjE);
    cudaGetSymbolAddress((void**)&part, g_part);

    int *degEgo = deg, *degE = deg + N;
    int *offEgo = off, *offE = off + (N + 1);
    int *curEgo = cur, *curE = cur + N;

    dim3 g128((N + 63) / 64, 2);
    int gf = (N + 63) / 64;
    int sg = (N * 32 + 255) / 256;
    int ntiles = (N + SCAN_TILE - 1) / SCAN_TILE;
    int maxE = (EGO > E) ? EGO : E;
    int eb4 = (maxE / 4 + 255) / 256;   // 4 edges per thread
    dim3 scang(ntiles, 2);

    // ---- CSR build + fp16 convert ----
    cudaMemsetAsync(deg, 0, 2 * N * sizeof(int), 0);
    build_front_kernel<<<eb4, 256>>>(ego, EGO, ei + E, E, degEgo, degE,
                                     x_in, xb, N * F / 4);
    scan_p1_kernel<<<scang, 256>>>(deg, N, part, ntiles);
    scan_p3_kernel<<<scang, 256>>>(deg, N, part, off, cur, ntiles, ntiles);
    fill2_kernel<<<eb4, 256>>>(ego, ego + EGO, EGO, ei + E, ei, E,
                               curEgo, curE, adjEgo, adjE);

    // ---- layer 0: Ego ----
    segsum128h_kernel<false><<<sg, 256>>>(xb, offEgo, adjEgo, ah, N, invN);
    gemm_h_kernel<<<g128, 256>>>(ah, W_ego0, b_ego0, yb0, N);
    // ---- layer 0: GIN ----
    segsum128h_kernel<true><<<sg, 256>>>(yb0, offE, adjE, ah, N, 1.0f);
    gemm_h_kernel<<<g128, 256>>>(ah, W_gin0, b_gin0, yb1, N);
    // ---- layer 1: Ego ----
    segsum128h_kernel<false><<<sg, 256>>>(yb1, offEgo, adjEgo, ah, N, invN);
    gemm_h_kernel<<<g128, 256>>>(ah, W_ego1, b_ego1, yb0, N);
    // ---- layer 1: GIN (direct x+aggr, fused GEMM+bias+log_softmax) ----
    segsum128h_kernel<true><<<sg, 256>>>(yb0, offE, adjE, ah, N, 1.0f);
    gemm47_lsm_kernel<<<gf, 256>>>(ah, W_gin1, b_gin1, (float*)d_out, N, OUTC);
}

// round 12
// speedup vs baseline: 1.0388x; 1.0388x over previous
#include <cuda_runtime.h>
#include <cuda_fp16.h>
#include <math.h>
#include <stdint.h>

#define F 128
#define MAXN 50000
#define MAXEGO 1250000
#define MAXE 700000
#define SCAN_TILE 1024
#define MAX_TILES 64

// fp16 activation buffers
__device__ __half g_xb[MAXN * F];
__device__ __half g_yb0[MAXN * F];
__device__ __half g_yb1[MAXN * F];
__device__ __half g_ah[MAXN * F];
// CSR scratch (list 0 = ego, list 1 = gin edges)
__device__ int g_deg[2 * MAXN];
__device__ int g_off[2 * (MAXN + 1)];
__device__ int g_adjEgo[MAXEGO];
__device__ int g_adjE[MAXE];
__device__ int g_rankEgo[MAXEGO];
__device__ int g_rankE[MAXE];
__device__ int g_part[2 * MAX_TILES];

// ---------------------------------------------------------------------------
// fused: histogram+rank both edge lists + fp32->fp16 convert of x (grid-stride).
// rank[e] = slot of edge e within its target's segment (coalesced store).
__global__ void build_front_kernel(const int* __restrict__ w0, int n0,
                                   const int* __restrict__ w1, int n1,
                                   int* __restrict__ deg0, int* __restrict__ deg1,
                                   int* __restrict__ rank0, int* __restrict__ rank1,
                                   const float* __restrict__ x, __half* __restrict__ y,
                                   int n4) {
    int i = blockIdx.x * blockDim.x + threadIdx.x;
    if (i < n0) rank0[i] = atomicAdd(&deg0[__ldg(w0 + i)], 1);
    if (i < n1) rank1[i] = atomicAdd(&deg1[__ldg(w1 + i)], 1);
    for (int j = i; j < n4; j += gridDim.x * blockDim.x) {
        float4 v = ((const float4*)x)[j];
        __half2 h0 = __floats2half2_rn(v.x, v.y);
        __half2 h1 = __floats2half2_rn(v.z, v.w);
        uint2 u;
        u.x = *(uint32_t*)&h0; u.y = *(uint32_t*)&h1;
        ((uint2*)y)[j] = u;
    }
}

// ---------------------------------------------------------------------------
// 2-phase exclusive scan, two lists via blockIdx.y.
__global__ void scan_p1_kernel(const int* __restrict__ deg, int n,
                               int* __restrict__ part, int ntiles) {
    __shared__ int ws[8];
    const int* d = deg + blockIdx.y * n;
    int* p = part + blockIdx.y * ntiles;
    int b = blockIdx.x, t = threadIdx.x;
    int base = b * SCAN_TILE + t * 4;
    int s = 0;
#pragma unroll
    for (int j = 0; j < 4; j++) {
        int i = base + j;
        if (i < n) s += __ldg(d + i);
    }
    int lane = t & 31, wid = t >> 5;
#pragma unroll
    for (int o = 16; o; o >>= 1) s += __shfl_down_sync(0xffffffffu, s, o);
    if (lane == 0) ws[wid] = s;
    __syncthreads();
    if (t < 8) {
        int v = ws[t];
#pragma unroll
        for (int o = 4; o; o >>= 1) v += __shfl_down_sync(0xffu, v, o);
        if (t == 0) p[b] = v;
    }
}

// p3 with in-block scan of partials. nb = #tiles (<=64). Writes off only.
__global__ void scan_p3_kernel(const int* __restrict__ deg, int n,
                               const int* __restrict__ part,
                               int* __restrict__ off, int ntiles, int nb) {
    __shared__ int ws[8];
    __shared__ int wtot[2];
    __shared__ int psc[MAX_TILES + 1];
    const int list = blockIdx.y;
    const int* d = deg + list * n;
    int* of = off + list * (n + 1);
    int b = blockIdx.x, t = threadIdx.x;

    int px = 0;
    if (t < 64) {
        int pv = (t < nb) ? __ldg(part + list * ntiles + t) : 0;
        int lane = t & 31, w = t >> 5;
        px = pv;
#pragma unroll
        for (int o = 1; o < 32; o <<= 1) {
            int u = __shfl_up_sync(0xffffffffu, px, o);
            if (lane >= o) px += u;
        }
        if (lane == 31) wtot[w] = px;
    }
    __syncthreads();
    if (t < 64) {
        int incl = px + ((t >> 5) ? wtot[0] : 0);
        psc[t + 1] = incl;
        if (t == 0) psc[0] = 0;
    }
    __syncthreads();
    if (b == 0 && t == 0) of[n] = psc[nb];
    const int tilebase = psc[b];

    int base = b * SCAN_TILE + t * 4;
    int v[4];
    int s = 0;
#pragma unroll
    for (int j = 0; j < 4; j++) {
        int i = base + j;
        v[j] = (i < n) ? __ldg(d + i) : 0;
        s += v[j];
    }
    int lane = t & 31, wid = t >> 5;
    int x = s;
#pragma unroll
    for (int o = 1; o < 32; o <<= 1) {
        int u = __shfl_up_sync(0xffffffffu, x, o);
        if (lane >= o) x += u;
    }
    if (lane == 31) ws[wid] = x;
    __syncthreads();
    if (wid == 0) {
        int w = (lane < 8) ? ws[lane] : 0;
#pragma unroll
        for (int o = 1; o < 8; o <<= 1) {
            int u = __shfl_up_sync(0xffffffffu, w, o);
            if (lane >= o) w += u;
        }
        if (lane < 8) ws[lane] = w;
    }
    __syncthreads();
    int run = tilebase + (x - s) + (wid ? ws[wid - 1] : 0);
#pragma unroll
    for (int j = 0; j < 4; j++) {
        int i = base + j;
        if (i < n) of[i] = run;
        run += v[j];
    }
}

// atomic-free fill: adj[off[w] + rank] = r  (all index loads coalesced).
__global__ void fill2_kernel(const int* __restrict__ w0, const int* __restrict__ r0, int n0,
                             const int* __restrict__ w1, const int* __restrict__ r1, int n1,
                             const int* __restrict__ rank0, const int* __restrict__ rank1,
                             const int* __restrict__ off0, const int* __restrict__ off1,
                             int* __restrict__ adj0, int* __restrict__ adj1) {
    int i = blockIdx.x * blockDim.x + threadIdx.x;
    if (i < n0) {
        int w = __ldg(w0 + i);
        adj0[__ldg(off0 + w) + __ldg(rank0 + i)] = __ldg(r0 + i);
    }
    if (i < n1) {
        int w = __ldg(w1 + i);
        adj1[__ldg(off1 + w) + __ldg(rank1 + i)] = __ldg(r1 + i);
    }
}

// ---------------------------------------------------------------------------
__device__ __forceinline__ void addh2(float2& a, uint32_t h) {
    float2 f = __half22float2(*(__half2*)&h);
    a.x += f.x; a.y += f.y;
}

// segsum over CSR, fp16 rows (uint2/lane) -> fp16 out. fp32 accumulate.
template <bool SELF>
__global__ void segsum128h_kernel(const __half* __restrict__ x,
                                  const int* __restrict__ off,
                                  const int* __restrict__ adj,
                                  __half* __restrict__ out, int n, float scale) {
    int gw = (blockIdx.x * blockDim.x + threadIdx.x) >> 5;
    int lane = threadIdx.x & 31;
    if (gw >= n) return;
    int s = __ldg(off + gw), e = __ldg(off + gw + 1);
    float2 acc0 = make_float2(0.f, 0.f), acc1 = make_float2(0.f, 0.f);
    if (SELF) {
        uint2 sv = __ldg((const uint2*)(x + (size_t)gw * 128) + lane);
        addh2(acc0, sv.x); addh2(acc1, sv.y);
    }
    for (int j = s; j < e; ) {
        int cnt = min(32, e - j);
        int my = (lane < cnt) ? __ldg(adj + j + lane) : 0;
        int k = 0;
        for (; k + 4 <= cnt; k += 4) {
            int r0 = __shfl_sync(0xffffffffu, my, k);
            int r1 = __shfl_sync(0xffffffffu, my, k + 1);
            int r2 = __shfl_sync(0xffffffffu, my, k + 2);
            int r3 = __shfl_sync(0xffffffffu, my, k + 3);
            uint2 u0 = __ldg((const uint2*)(x + (size_t)r0 * 128) + lane);
            uint2 u1 = __ldg((const uint2*)(x + (size_t)r1 * 128) + lane);
            uint2 u2 = __ldg((const uint2*)(x + (size_t)r2 * 128) + lane);
            uint2 u3 = __ldg((const uint2*)(x + (size_t)r3 * 128) + lane);
            addh2(acc0, u0.x); addh2(acc1, u0.y);
            addh2(acc0, u1.x); addh2(acc1, u1.y);
            addh2(acc0, u2.x); addh2(acc1, u2.y);
            addh2(acc0, u3.x); addh2(acc1, u3.y);
        }
        for (; k < cnt; k++) {
            int r0 = __shfl_sync(0xffffffffu, my, k);
            uint2 u0 = __ldg((const uint2*)(x + (size_t)r0 * 128) + lane);
            addh2(acc0, u0.x); addh2(acc1, u0.y);
        }
        j += cnt;
    }
    __half2 h0 = __floats2half2_rn(acc0.x * scale, acc0.y * scale);
    __half2 h1 = __floats2half2_rn(acc1.x * scale, acc1.y * scale);
    uint2 o;
    o.x = *(uint32_t*)&h0; o.y = *(uint32_t*)&h1;
    *(uint2*)(out + (size_t)gw * 128 + lane * 4) = o;
}

// ---------------------------------------------------------------------------
__device__ __forceinline__ void mma_f16(float& c0, float& c1, float& c2, float& c3,
                                        uint32_t a0, uint32_t a1, uint32_t a2, uint32_t a3,
                                        uint32_t b0, uint32_t b1) {
    asm volatile(
        "mma.sync.aligned.m16n8k16.row.col.f32.f16.f16.f32 "
        "{%0,%1,%2,%3}, {%4,%5,%6,%7}, {%8,%9}, {%0,%1,%2,%3};"
        : "+f"(c0), "+f"(c1), "+f"(c2), "+f"(c3)
        : "r"(a0), "r"(a1), "r"(a2), "r"(a3), "r"(b0), "r"(b1));
}

// fp16 GEMM: C = relu(Ah @ W + b), 64x64 tile per CTA, grid.y = col tile of 64.
__global__ void __launch_bounds__(256, 4)
gemm_h_kernel(const __half* __restrict__ Ah,
              const float* __restrict__ W, const float* __restrict__ bias,
              __half* __restrict__ Ch, int M) {
    constexpr int PWH = 136;
    constexpr int PAH = 136;
    __shared__ __half Wt[64 * PWH];
    __shared__ __half As[64 * PAH];
    __shared__ float bs[64];

    const int tid  = threadIdx.x;
    const int lane = tid & 31;
    const int warp = tid >> 5;
    const int cb   = blockIdx.y * 64;
    const int base = blockIdx.x * 64;

    {
        int tn = tid & 63;
        int gc = cb + tn;
        for (int kb = (tid >> 6) * 8; kb < 128; kb += 32) {
            __half tmp[8];
#pragma unroll
            for (int j = 0; j < 8; j++)
                tmp[j] = __float2half_rn(__ldg(W + (size_t)(kb + j) * 128 + gc));
            *(uint4*)(Wt + tn * PWH + kb) = *(uint4*)tmp;
        }
    }
    if (tid < 64) bs[tid] = __ldg(bias + cb + tid);

#pragma unroll
    for (int u = tid; u < 64 * 16; u += 256) {
        int rr = u >> 4, c8 = u & 15;
        int row = base + rr;
        uint4 hv = make_uint4(0u, 0u, 0u, 0u);
        if (row < M) hv = __ldg((const uint4*)(Ah + (size_t)row * 128) + c8);
        *(uint4*)(As + rr * PAH + c8 * 8) = hv;
    }
    __syncthreads();

    const int wr = warp >> 1, wc = warp & 1;
    const int g = lane >> 2, t = lane & 3;
    float acc[4][4];
#pragma unroll
    for (int nt = 0; nt < 4; nt++)
#pragma unroll
        for (int j = 0; j < 4; j++) acc[nt][j] = 0.f;

    const int r0 = wr * 16 + g;
    const __half* arow0 = As + r0 * PAH;
    const __half* arow1 = As + (r0 + 8) * PAH;
#pragma unroll
    for (int ks = 0; ks < 8; ks++) {
        const int k0 = ks * 16;
        uint32_t a0 = *(const uint32_t*)(arow0 + k0 + 2 * t);
        uint32_t a1 = *(const uint32_t*)(arow1 + k0 + 2 * t);
        uint32_t a2 = *(const uint32_t*)(arow0 + k0 + 2 * t + 8);
        uint32_t a3 = *(const uint32_t*)(arow1 + k0 + 2 * t + 8);
#pragma unroll
        for (int nt = 0; nt < 4; nt++) {
            int n = wc * 32 + nt * 8 + g;
            uint32_t b0 = *(const uint32_t*)(Wt + n * PWH + k0 + 2 * t);
            uint32_t b1 = *(const uint32_t*)(Wt + n * PWH + k0 + 2 * t + 8);
            mma_f16(acc[nt][0], acc[nt][1], acc[nt][2], acc[nt][3],
                    a0, a1, a2, a3, b0, b1);
        }
    }

    int gr0 = base + wr * 16 + g;
    int gr1 = gr0 + 8;
#pragma unroll
    for (int nt = 0; nt < 4; nt++) {
        int col = wc * 32 + nt * 8 + t * 2;
        float bx = bs[col], by = bs[col + 1];
        __half2 h0 = __floats2half2_rn(fmaxf(acc[nt][0] + bx, 0.f), fmaxf(acc[nt][1] + by, 0.f));
        __half2 h1 = __floats2half2_rn(fmaxf(acc[nt][2] + bx, 0.f), fmaxf(acc[nt][3] + by, 0.f));
        int gcol = cb + col;
        if (gr0 < M) *(__half2*)(Ch + (size_t)gr0 * 128 + gcol) = h0;
        if (gr1 < M) *(__half2*)(Ch + (size_t)gr1 * 128 + gcol) = h1;
    }
}

// final GEMM + bias + log_softmax fused: out = log_softmax(Ah @ W + b) (47 cols).
__global__ void __launch_bounds__(256, 4)
gemm47_lsm_kernel(const __half* __restrict__ Ah, const float* __restrict__ W,
                  const float* __restrict__ bias,
                  float* __restrict__ outp, int M, int nca) {
    constexpr int PWH = 136;
    constexpr int PAH = 136;
    constexpr int LP = 65;
    __shared__ __half Wt[64 * PWH];   // reused as logits after MMA
    __shared__ __half As[64 * PAH];
    __shared__ float bs[64];

    const int tid  = threadIdx.x;
    const int lane = tid & 31;
    const int warp = tid >> 5;
    const int base = blockIdx.x * 64;

    {
        int tn = tid & 63;
        for (int kb = (tid >> 6) * 8; kb < 128; kb += 32) {
            __half tmp[8];
#pragma unroll
            for (int j = 0; j < 8; j++) {
                float w = (tn < nca) ? __ldg(W + (size_t)(kb + j) * nca + tn) : 0.f;
                tmp[j] = __float2half_rn(w);
            }
            *(uint4*)(Wt + tn * PWH + kb) = *(uint4*)tmp;
        }
    }
    if (tid < 64) bs[tid] = (tid < nca) ? __ldg(bias + tid) : 0.f;
#pragma unroll
    for (int u = tid; u < 64 * 16; u += 256) {
        int rr = u >> 4, c8 = u & 15;
        int row = base + rr;
        uint4 hv = make_uint4(0u, 0u, 0u, 0u);
        if (row < M) hv = __ldg((const uint4*)(Ah + (size_t)row * 128) + c8);
        *(uint4*)(As + rr * PAH + c8 * 8) = hv;
    }
    __syncthreads();

    const int wr = warp >> 1, wc = warp & 1;
    const int g = lane >> 2, t = lane & 3;
    float acc[4][4];
#pragma unroll
    for (int nt = 0; nt < 4; nt++)
#pragma unroll
        for (int j = 0; j < 4; j++) acc[nt][j] = 0.f;

    const int r0 = wr * 16 + g;
    const __half* arow0 = As + r0 * PAH;
    const __half* arow1 = As + (r0 + 8) * PAH;
#pragma unroll
    for (int ks = 0; ks < 8; ks++) {
        const int k0 = ks * 16;
        uint32_t a0 = *(const uint32_t*)(arow0 + k0 + 2 * t);
        uint32_t a1 = *(const uint32_t*)(arow1 + k0 + 2 * t);
        uint32_t a2 = *(const uint32_t*)(arow0 + k0 + 2 * t + 8);
        uint32_t a3 = *(const uint32_t*)(arow1 + k0 + 2 * t + 8);
#pragma unroll
        for (int nt = 0; nt < 4; nt++) {
            int n = wc * 32 + nt * 8 + g;
            uint32_t b0 = *(const uint32_t*)(Wt + n * PWH + k0 + 2 * t);
            uint32_t b1 = *(const uint32_t*)(Wt + n * PWH + k0 + 2 * t + 8);
            mma_f16(acc[nt][0], acc[nt][1], acc[nt][2], acc[nt][3],
                    a0, a1, a2, a3, b0, b1);
        }
    }
    __syncthreads();  // all Wt reads done; reuse as logits

    float* lg = (float*)Wt;  // [64][LP]
#pragma unroll
    for (int nt = 0; nt < 4; nt++) {
        int col = wc * 32 + nt * 8 + t * 2;
        float bx = bs[col], by = bs[col + 1];
        int lr0 = wr * 16 + g, lr1 = lr0 + 8;
        lg[lr0 * LP + col]     = acc[nt][0] + bx;
        lg[lr0 * LP + col + 1] = acc[nt][1] + by;
        lg[lr1 * LP + col]     = acc[nt][2] + bx;
        lg[lr1 * LP + col + 1] = acc[nt][3] + by;
    }
    __syncthreads();

    for (int r = warp; r < 64; r += 8) {
        int row = base + r;
        if (row >= M) continue;
        int c2 = lane + 32;
        float v1 = (lane < nca) ? lg[r * LP + lane] : -INFINITY;
        float v2 = (c2 < nca)   ? lg[r * LP + c2]   : -INFINITY;
        float mx = fmaxf(v1, v2);
#pragma unroll
        for (int o = 16; o; o >>= 1) mx = fmaxf(mx, __shfl_xor_sync(0xffffffffu, mx, o));
        float s = ((lane < nca) ? expf(v1 - mx) : 0.f) + ((c2 < nca) ? expf(v2 - mx) : 0.f);
#pragma unroll
        for (int o = 16; o; o >>= 1) s += __shfl_xor_sync(0xffffffffu, s, o);
        float lgn = logf(s) + mx;
        float* orow = outp + (size_t)row * nca;
        if (lane < nca) orow[lane] = v1 - lgn;
        if (c2 < nca)   orow[c2]   = v2 - lgn;
    }
}

// ---------------------------------------------------------------------------
extern "C" void kernel_launch(void* const* d_in, const int* in_sizes, int n_in,
                              void* d_out, int out_size) {
    const float* x_in   = (const float*)d_in[0];
    const int*   ei     = (const int*)d_in[1];
    const int*   ego    = (const int*)d_in[2];
    const float* W_ego0 = (const float*)d_in[3];
    const float* b_ego0 = (const float*)d_in[4];
    const float* W_gin0 = (const float*)d_in[5];
    const float* b_gin0 = (const float*)d_in[6];
    const float* W_ego1 = (const float*)d_in[7];
    const float* b_ego1 = (const float*)d_in[8];
    const float* W_gin1 = (const float*)d_in[9];
    const float* b_gin1 = (const float*)d_in[10];

    int N    = in_sizes[0] / F;
    int E    = in_sizes[1] / 2;
    int EGO  = in_sizes[2] / 2;
    int OUTC = in_sizes[10];
    float invN = 1.0f / (float)N;

    __half *xb, *yb0, *yb1, *ah;
    int *deg, *off, *adjEgo, *adjE, *rankEgo, *rankE, *part;
    cudaGetSymbolAddress((void**)&xb, g_xb);
    cudaGetSymbolAddress((void**)&yb0, g_yb0);
    cudaGetSymbolAddress((void**)&yb1, g_yb1);
    cudaGetSymbolAddress((void**)&ah, g_ah);
    cudaGetSymbolAddress((void**)&deg, g_deg);
    cudaGetSymbolAddress((void**)&off, g_off);
    cudaGetSymbolAddress((void**)&adjEgo, g_adjEgo);
    cudaGetSymbolAddress((void**)&adjE, g_adjE);
    cudaGetSymbolAddress((void**)&rankEgo, g_rankEgo);
    cudaGetSymbolAddress((void**)&rankE, g_rankE);
    cudaGetSymbolAddress((void**)&part, g_part);

    int *degEgo = deg, *degE = deg + N;
    int *offEgo = off, *offE = off + (N + 1);

    dim3 g128((N + 63) / 64, 2);
    int gf = (N + 63) / 64;
    int sg = (N * 32 + 255) / 256;
    int ntiles = (N + SCAN_TILE - 1) / SCAN_TILE;
    int maxE = (EGO > E) ? EGO : E;
    int eb = (maxE + 255) / 256;
    dim3 scang(ntiles, 2);

    // ---- CSR build + fp16 convert ----
    cudaMemsetAsync(deg, 0, 2 * N * sizeof(int), 0);
    build_front_kernel<<<eb, 256>>>(ego, EGO, ei + E, E, degEgo, degE,
                                    rankEgo, rankE, x_in, xb, N * F / 4);
    scan_p1_kernel<<<scang, 256>>>(deg, N, part, ntiles);
    scan_p3_kernel<<<scang, 256>>>(deg, N, part, off, ntiles, ntiles);
    fill2_kernel<<<eb, 256>>>(ego, ego + EGO, EGO, ei + E, ei, E,
                              rankEgo, rankE, offEgo, offE, adjEgo, adjE);

    // ---- layer 0: Ego ----
    segsum128h_kernel<false><<<sg, 256>>>(xb, offEgo, adjEgo, ah, N, invN);
    gemm_h_kernel<<<g128, 256>>>(ah, W_ego0, b_ego0, yb0, N);
    // ---- layer 0: GIN ----
    segsum128h_kernel<true><<<sg, 256>>>(yb0, offE, adjE, ah, N, 1.0f);
    gemm_h_kernel<<<g128, 256>>>(ah, W_gin0, b_gin0, yb1, N);
    // ---- layer 1: Ego ----
    segsum128h_kernel<false><<<sg, 256>>>(yb1, offEgo, adjEgo, ah, N, invN);
    gemm_h_kernel<<<g128, 256>>>(ah, W_ego1, b_ego1, yb0, N);
    // ---- layer 1: GIN (direct x+aggr, fused GEMM+bias+log_softmax) ----
    segsum128h_kernel<true><<<sg, 256>>>(yb0, offE, adjE, ah, N, 1.0f);
    gemm47_lsm_kernel<<<gf, 256>>>(ah, W_gin1, b_gin1, (float*)d_out, N, OUTC);
}